// round 14
// baseline (speedup 1.0000x reference)
#include <cuda_runtime.h>
#include <cstdint>

#define W_POS 5
#define W_NEG 10
#define N_SAMP 15
#define EMBED_DIM 128
#define NUM_TYPES 4
#define EPS 1e-15f

__global__ __launch_bounds__(256) void mp2vec_kernel(
    const float* __restrict__ start_embeds,   // [NODE_SIZE, 128]
    const float* __restrict__ end_embeds,     // [NODE_SIZE, 4, 128]
    const int* __restrict__ start_node,       // [B, 1]
    const int* __restrict__ pos_samples,      // [B, 5]
    const int* __restrict__ neg_samples,      // [B, 10]
    const int* __restrict__ node_types,       // [NODE_SIZE]
    float* __restrict__ out,                  // [B]
    int B)
{
    const int warp_id = (blockIdx.x * blockDim.x + threadIdx.x) >> 5;
    if (warp_id >= B) return;
    const int lane = threadIdx.x & 31;

    const int s = __ldg(start_node + warp_id);
    const int t = __ldg(node_types + s);

    // start embedding: lane owns 4 consecutive floats (16B) -> coalesced 512B/warp
    const float4 se = *reinterpret_cast<const float4*>(
        (const char*)start_embeds + (uint32_t)s * 512u + (uint32_t)lane * 16u);

    // Load 15 sample indices (warp-uniform broadcasts; neg rows are 8B-aligned -> int2)
    int idxs[N_SAMP];
#pragma unroll
    for (int w = 0; w < W_POS; w++)
        idxs[w] = __ldg(pos_samples + warp_id * W_POS + w);
    {
        const int2* nrow = reinterpret_cast<const int2*>(neg_samples + warp_id * W_NEG);
#pragma unroll
        for (int j = 0; j < W_NEG / 2; j++) {
            int2 p = __ldg(nrow + j);
            idxs[W_POS + 2 * j]     = p.x;
            idxs[W_POS + 2 * j + 1] = p.y;
        }
    }

    // Gather base: end_embeds + t*512B + lane*16B; per-sample offset fits in u32
    const char* ebase = (const char*)end_embeds + (uint32_t)t * 512u + (uint32_t)lane * 16u;

    float4 es[N_SAMP];
#pragma unroll
    for (int w = 0; w < N_SAMP; w++)
        es[w] = *reinterpret_cast<const float4*>(ebase + (uint32_t)idxs[w] * 2048u);

    // Per-lane partial dots (sample 15 is a dummy zero to make K=16)
    float v[16];
#pragma unroll
    for (int w = 0; w < N_SAMP; w++)
        v[w] = se.x * es[w].x + se.y * es[w].y + se.z * es[w].z + se.w * es[w].w;
    v[15] = 0.0f;

    // Reduce-scatter: 16 shuffles total; lane l ends with sample (l>>1)&15 fully reduced
    float v8[8];
#pragma unroll
    for (int j = 0; j < 8; j++) {
        float send = (lane & 16) ? v[j] : v[j + 8];
        float keep = (lane & 16) ? v[j + 8] : v[j];
        v8[j] = keep + __shfl_xor_sync(0xffffffffu, send, 16);
    }
    float v4[4];
#pragma unroll
    for (int j = 0; j < 4; j++) {
        float send = (lane & 8) ? v8[j] : v8[j + 4];
        float keep = (lane & 8) ? v8[j + 4] : v8[j];
        v4[j] = keep + __shfl_xor_sync(0xffffffffu, send, 8);
    }
    float v2[2];
#pragma unroll
    for (int j = 0; j < 2; j++) {
        float send = (lane & 4) ? v4[j] : v4[j + 2];
        float keep = (lane & 4) ? v4[j + 2] : v4[j];
        v2[j] = keep + __shfl_xor_sync(0xffffffffu, send, 4);
    }
    float s1;
    {
        float send = (lane & 2) ? v2[0] : v2[1];
        float keep = (lane & 2) ? v2[1] : v2[0];
        s1 = keep + __shfl_xor_sync(0xffffffffu, send, 2);
    }
    const float dot = s1 + __shfl_xor_sync(0xffffffffu, s1, 1);

    // Distributed epilogue: lane pair (2l, 2l+1) both hold sample w = lane>>1.
    // Each contributes half the sample's term; dummy sample 15 contributes 0.
    const int w = (lane >> 1) & 15;
    const float p = 1.0f / (1.0f + expf(-dot));
    const float arg = (w < W_POS) ? (p + EPS) : (1.0f - p + EPS);
    // coef = -1/(2*W_POS) or -1/(2*W_NEG) (the 1/2 accounts for pair duplication)
    float coef = (w < W_POS) ? (-0.5f / W_POS) : (-0.5f / W_NEG);
    if (w == 15) coef = 0.0f;
    float term = coef * logf(arg);

    // Final sum of 32 per-lane terms
#pragma unroll
    for (int off = 16; off > 0; off >>= 1)
        term += __shfl_xor_sync(0xffffffffu, term, off);

    if (lane == 0) out[warp_id] = term;
}

extern "C" void kernel_launch(void* const* d_in, const int* in_sizes, int n_in,
                              void* d_out, int out_size) {
    const float* start_embeds = (const float*)d_in[0];
    const float* end_embeds   = (const float*)d_in[1];
    const int*   start_node   = (const int*)d_in[2];
    const int*   pos_samples  = (const int*)d_in[3];
    const int*   neg_samples  = (const int*)d_in[4];
    const int*   node_types   = (const int*)d_in[5];
    float*       out          = (float*)d_out;

    const int B = out_size;
    const int threads = 256;                       // 8 warps/block
    const int warps_per_block = threads / 32;
    const int blocks = (B + warps_per_block - 1) / warps_per_block;
    mp2vec_kernel<<<blocks, threads>>>(start_embeds, end_embeds, start_node,
                                       pos_samples, neg_samples, node_types, out, B);
}

// round 15
// speedup vs baseline: 1.0163x; 1.0163x over previous
#include <cuda_runtime.h>
#include <cstdint>

#define W_POS 5
#define W_NEG 10
#define N_SAMP 15
#define EMBED_DIM 128
#define NUM_TYPES 4
#define EPS 1e-15f

__global__ __launch_bounds__(256) void mp2vec_kernel(
    const float* __restrict__ start_embeds,   // [NODE_SIZE, 128]
    const float* __restrict__ end_embeds,     // [NODE_SIZE, 4, 128]
    const int* __restrict__ start_node,       // [B, 1]
    const int* __restrict__ pos_samples,      // [B, 5]
    const int* __restrict__ neg_samples,      // [B, 10]
    const int* __restrict__ node_types,       // [NODE_SIZE]
    float* __restrict__ out,                  // [B]
    int B)
{
    const int warp_id = (blockIdx.x * blockDim.x + threadIdx.x) >> 5;
    if (warp_id >= B) return;
    const int lane = threadIdx.x & 31;

    const int s = __ldg(start_node + warp_id);
    const int t = __ldg(node_types + s);

    // start embedding: lane owns 4 consecutive floats (16B) -> coalesced 512B/warp
    const float4 se = *reinterpret_cast<const float4*>(
        (const char*)start_embeds + (uint32_t)s * 512u + (uint32_t)lane * 16u);

    // Load 15 sample indices (warp-uniform broadcasts; neg rows are 8B-aligned -> int2)
    int idxs[N_SAMP];
#pragma unroll
    for (int w = 0; w < W_POS; w++)
        idxs[w] = __ldg(pos_samples + warp_id * W_POS + w);
    {
        const int2* nrow = reinterpret_cast<const int2*>(neg_samples + warp_id * W_NEG);
#pragma unroll
        for (int j = 0; j < W_NEG / 2; j++) {
            int2 p = __ldg(nrow + j);
            idxs[W_POS + 2 * j]     = p.x;
            idxs[W_POS + 2 * j + 1] = p.y;
        }
    }

    // Gather base: end_embeds + t*512B + lane*16B; per-sample offset fits in u32
    const char* ebase = (const char*)end_embeds + (uint32_t)t * 512u + (uint32_t)lane * 16u;

    float4 es[N_SAMP];
#pragma unroll
    for (int w = 0; w < N_SAMP; w++)
        es[w] = *reinterpret_cast<const float4*>(ebase + (uint32_t)idxs[w] * 2048u);

    // Per-lane partial dots (sample 15 is a dummy zero to make K=16)
    float v[16];
#pragma unroll
    for (int w = 0; w < N_SAMP; w++)
        v[w] = se.x * es[w].x + se.y * es[w].y + se.z * es[w].z + se.w * es[w].w;
    v[15] = 0.0f;

    // Reduce-scatter: 16 shuffles total; lane l ends with sample (l>>1)&15 fully reduced
    float v8[8];
#pragma unroll
    for (int j = 0; j < 8; j++) {
        float send = (lane & 16) ? v[j] : v[j + 8];
        float keep = (lane & 16) ? v[j + 8] : v[j];
        v8[j] = keep + __shfl_xor_sync(0xffffffffu, send, 16);
    }
    float v4[4];
#pragma unroll
    for (int j = 0; j < 4; j++) {
        float send = (lane & 8) ? v8[j] : v8[j + 4];
        float keep = (lane & 8) ? v8[j + 4] : v8[j];
        v4[j] = keep + __shfl_xor_sync(0xffffffffu, send, 8);
    }
    float v2[2];
#pragma unroll
    for (int j = 0; j < 2; j++) {
        float send = (lane & 4) ? v4[j] : v4[j + 2];
        float keep = (lane & 4) ? v4[j + 2] : v4[j];
        v2[j] = keep + __shfl_xor_sync(0xffffffffu, send, 4);
    }
    float s1;
    {
        float send = (lane & 2) ? v2[0] : v2[1];
        float keep = (lane & 2) ? v2[1] : v2[0];
        s1 = keep + __shfl_xor_sync(0xffffffffu, send, 2);
    }
    const float dot = s1 + __shfl_xor_sync(0xffffffffu, s1, 1);

    // Distributed epilogue: lane pair (2l, 2l+1) both hold sample w = lane>>1.
    // Each contributes half the sample's term; dummy sample 15 contributes 0.
    const int w = (lane >> 1) & 15;
    const float p = 1.0f / (1.0f + expf(-dot));
    const float arg = (w < W_POS) ? (p + EPS) : (1.0f - p + EPS);
    // coef = -1/(2*W_POS) or -1/(2*W_NEG) (the 1/2 accounts for pair duplication)
    float coef = (w < W_POS) ? (-0.5f / W_POS) : (-0.5f / W_NEG);
    if (w == 15) coef = 0.0f;
    float term = coef * logf(arg);

    // Final sum of 32 per-lane terms
#pragma unroll
    for (int off = 16; off > 0; off >>= 1)
        term += __shfl_xor_sync(0xffffffffu, term, off);

    if (lane == 0) out[warp_id] = term;
}

extern "C" void kernel_launch(void* const* d_in, const int* in_sizes, int n_in,
                              void* d_out, int out_size) {
    const float* start_embeds = (const float*)d_in[0];
    const float* end_embeds   = (const float*)d_in[1];
    const int*   start_node   = (const int*)d_in[2];
    const int*   pos_samples  = (const int*)d_in[3];
    const int*   neg_samples  = (const int*)d_in[4];
    const int*   node_types   = (const int*)d_in[5];
    float*       out          = (float*)d_out;

    const int B = out_size;
    const int threads = 256;                       // 8 warps/block
    const int warps_per_block = threads / 32;
    const int blocks = (B + warps_per_block - 1) / warps_per_block;
    mp2vec_kernel<<<blocks, threads>>>(start_embeds, end_embeds, start_node,
                                       pos_samples, neg_samples, node_types, out, B);
}

// round 17
// speedup vs baseline: 1.0187x; 1.0024x over previous
#include <cuda_runtime.h>
#include <cstdint>

#define W_POS 5
#define W_NEG 10
#define N_SAMP 15
#define EMBED_DIM 128
#define NUM_TYPES 4
#define EPS 1e-15f

__global__ __launch_bounds__(256) void mp2vec_kernel(
    const float* __restrict__ start_embeds,   // [NODE_SIZE, 128]
    const float* __restrict__ end_embeds,     // [NODE_SIZE, 4, 128]
    const int* __restrict__ start_node,       // [B, 1]
    const int* __restrict__ pos_samples,      // [B, 5]
    const int* __restrict__ neg_samples,      // [B, 10]
    const int* __restrict__ node_types,       // [NODE_SIZE]
    float* __restrict__ out,                  // [B]
    int B)
{
    const int warp_id = (blockIdx.x * blockDim.x + threadIdx.x) >> 5;
    if (warp_id >= B) return;
    const int lane = threadIdx.x & 31;

    const int s = __ldg(start_node + warp_id);
    const int t = __ldg(node_types + s);

    // start embedding: lane owns 4 consecutive floats (16B) -> coalesced 512B/warp
    const float4 se = *reinterpret_cast<const float4*>(
        (const char*)start_embeds + (uint32_t)s * 512u + (uint32_t)lane * 16u);

    // Load 15 sample indices (warp-uniform broadcasts; neg rows are 8B-aligned -> int2)
    int idxs[N_SAMP];
#pragma unroll
    for (int w = 0; w < W_POS; w++)
        idxs[w] = __ldg(pos_samples + warp_id * W_POS + w);
    {
        const int2* nrow = reinterpret_cast<const int2*>(neg_samples + warp_id * W_NEG);
#pragma unroll
        for (int j = 0; j < W_NEG / 2; j++) {
            int2 p = __ldg(nrow + j);
            idxs[W_POS + 2 * j]     = p.x;
            idxs[W_POS + 2 * j + 1] = p.y;
        }
    }

    // Gather base: end_embeds + t*512B + lane*16B; per-sample offset fits in u32
    const char* ebase = (const char*)end_embeds + (uint32_t)t * 512u + (uint32_t)lane * 16u;

    float4 es[N_SAMP];
#pragma unroll
    for (int w = 0; w < N_SAMP; w++)
        es[w] = *reinterpret_cast<const float4*>(ebase + (uint32_t)idxs[w] * 2048u);

    // Per-lane partial dots (sample 15 is a dummy zero to make K=16)
    float v[16];
#pragma unroll
    for (int w = 0; w < N_SAMP; w++)
        v[w] = se.x * es[w].x + se.y * es[w].y + se.z * es[w].z + se.w * es[w].w;
    v[15] = 0.0f;

    // Reduce-scatter: 16 shuffles total; lane l ends with sample (l>>1)&15 fully reduced
    float v8[8];
#pragma unroll
    for (int j = 0; j < 8; j++) {
        float send = (lane & 16) ? v[j] : v[j + 8];
        float keep = (lane & 16) ? v[j + 8] : v[j];
        v8[j] = keep + __shfl_xor_sync(0xffffffffu, send, 16);
    }
    float v4[4];
#pragma unroll
    for (int j = 0; j < 4; j++) {
        float send = (lane & 8) ? v8[j] : v8[j + 4];
        float keep = (lane & 8) ? v8[j + 4] : v8[j];
        v4[j] = keep + __shfl_xor_sync(0xffffffffu, send, 8);
    }
    float v2[2];
#pragma unroll
    for (int j = 0; j < 2; j++) {
        float send = (lane & 4) ? v4[j] : v4[j + 2];
        float keep = (lane & 4) ? v4[j + 2] : v4[j];
        v2[j] = keep + __shfl_xor_sync(0xffffffffu, send, 4);
    }
    float s1;
    {
        float send = (lane & 2) ? v2[0] : v2[1];
        float keep = (lane & 2) ? v2[1] : v2[0];
        s1 = keep + __shfl_xor_sync(0xffffffffu, send, 2);
    }
    const float dot = s1 + __shfl_xor_sync(0xffffffffu, s1, 1);

    // Distributed epilogue: lane pair (2l, 2l+1) both hold sample w = lane>>1.
    // Each contributes half the sample's term; dummy sample 15 contributes 0.
    const int w = (lane >> 1) & 15;
    const float p = 1.0f / (1.0f + expf(-dot));
    const float arg = (w < W_POS) ? (p + EPS) : (1.0f - p + EPS);
    // coef = -1/(2*W_POS) or -1/(2*W_NEG) (the 1/2 accounts for pair duplication)
    float coef = (w < W_POS) ? (-0.5f / W_POS) : (-0.5f / W_NEG);
    if (w == 15) coef = 0.0f;
    float term = coef * logf(arg);

    // Final sum of 32 per-lane terms
#pragma unroll
    for (int off = 16; off > 0; off >>= 1)
        term += __shfl_xor_sync(0xffffffffu, term, off);

    if (lane == 0) out[warp_id] = term;
}

extern "C" void kernel_launch(void* const* d_in, const int* in_sizes, int n_in,
                              void* d_out, int out_size) {
    const float* start_embeds = (const float*)d_in[0];
    const float* end_embeds   = (const float*)d_in[1];
    const int*   start_node   = (const int*)d_in[2];
    const int*   pos_samples  = (const int*)d_in[3];
    const int*   neg_samples  = (const int*)d_in[4];
    const int*   node_types   = (const int*)d_in[5];
    float*       out          = (float*)d_out;

    const int B = out_size;
    const int threads = 256;                       // 8 warps/block
    const int warps_per_block = threads / 32;
    const int blocks = (B + warps_per_block - 1) / warps_per_block;
    mp2vec_kernel<<<blocks, threads>>>(start_embeds, end_embeds, start_node,
                                       pos_samples, neg_samples, node_types, out, B);
}